// round 4
// baseline (speedup 1.0000x reference)
#include <cuda_runtime.h>
#include <math.h>

#define BATCH 16
#define SEQ   512
#define DIM   1024
#define NH    16
#define HD    64
#define MROWS (BATCH*SEQ)

// ---------------- scratch (no cudaMalloc allowed) ----------------
__device__ float g_q[(size_t)MROWS*DIM];                 // [b*SEQ+s][h*HD+d]
__device__ float g_k[(size_t)MROWS*DIM];
__device__ float g_v[(size_t)MROWS*DIM];
__device__ float g_attn[(size_t)MROWS*DIM];
__device__ float g_scores[(size_t)BATCH*NH*SEQ*SEQ];     // [bh][q][k], 256 MB
__device__ float g_cos[SEQ][HD];
__device__ float g_sin[SEQ][HD];

// ---------------- C = A @ B^T (verified simple tiled GEMM, unchanged from R3) ----------------
template<int MODE>
__global__ __launch_bounds__(256)
void gemm_simple(const float* __restrict__ Ain, const float* __restrict__ Bw,
                 float* __restrict__ Cout) {
    __shared__ float As[32][33];
    __shared__ float Bs[32][33];

    const float* A = (MODE == 3) ? (const float*)g_attn : Ain;
    float* C = (MODE == 0) ? g_q : (MODE == 1) ? g_k : (MODE == 2) ? g_v : Cout;

    const int bm = blockIdx.y * 32;
    const int bn = blockIdx.x * 32;
    const int tx = threadIdx.x;
    const int ty = threadIdx.y;

    float acc[4] = {0.f, 0.f, 0.f, 0.f};

    for (int kt = 0; kt < DIM; kt += 32) {
#pragma unroll
        for (int i = 0; i < 4; i++) {
            As[ty + 8*i][tx] = A [(size_t)(bm + ty + 8*i) * DIM + kt + tx];
            Bs[ty + 8*i][tx] = Bw[(size_t)(bn + ty + 8*i) * DIM + kt + tx];
        }
        __syncthreads();
#pragma unroll
        for (int k = 0; k < 32; k++) {
            const float b = Bs[tx][k];
#pragma unroll
            for (int i = 0; i < 4; i++)
                acc[i] = fmaf(As[ty + 8*i][k], b, acc[i]);
        }
        __syncthreads();
    }
#pragma unroll
    for (int i = 0; i < 4; i++)
        C[(size_t)(bm + ty + 8*i) * DIM + bn + tx] = acc[i];
}

// ---------------- literal rope tables: inv_freq = 1/10000^(2i/64), emb = [freqs, freqs] ----------------
__global__ void rope_tables() {
    const int idx = blockIdx.x * 256 + threadIdx.x;   // SEQ*32 threads
    const int s = idx >> 5, i = idx & 31;
    const double inv = pow(10000.0, -((double)(2*i)) / 64.0);
    const double f = (double)s * inv;
    const float c = (float)cos(f);
    const float sn = (float)sin(f);
    g_cos[s][i] = c;  g_cos[s][i+32] = c;
    g_sin[s][i] = sn; g_sin[s][i+32] = sn;
}

// ---------------- literal rope apply: q = q*cos + rotate_half(q)*sin (in place on g_q/g_k) ----------------
__global__ void rope_apply() {
    const int idx = blockIdx.x * 256 + threadIdx.x;   // MROWS*NH*32 threads
    const int i = idx & 31;
    const int h = (idx >> 5) & 15;
    const int m = idx >> 9;            // b*SEQ + s
    const int s = m & (SEQ-1);
    const float c  = g_cos[s][i];
    const float sn = g_sin[s][i];
    const size_t base = (size_t)m * DIM + h*HD + i;
    float x1 = g_q[base], x2 = g_q[base + 32];
    g_q[base]      = x1*c - x2*sn;     // rotate_half: first half gets -x2
    g_q[base + 32] = x2*c + x1*sn;     // second half gets +x1
    x1 = g_k[base]; x2 = g_k[base + 32];
    g_k[base]      = x1*c - x2*sn;
    g_k[base + 32] = x2*c + x1*sn;
}

// ---------------- scores[bh][q][k] = (q.k)/8, masked to -1e30 where k > q ----------------
// grid (SEQ/64, BATCH*NH), 256 threads; thread owns 4x4 of each 64x64 (q,k) tile.
__global__ __launch_bounds__(256)
void scores_kernel() {
    __shared__ float Qs[64][65];
    __shared__ float Ks[64][65];
    const int qt = blockIdx.x;
    const int bh = blockIdx.y;
    const int b = bh / NH, h = bh % NH;
    const int tid = threadIdx.x;
    const int ty = tid >> 4, tx = tid & 15;

    for (int e = tid; e < 64*64; e += 256) {
        int r = e >> 6, d = e & 63;
        Qs[r][d] = g_q[(size_t)(b*SEQ + qt*64 + r) * DIM + h*HD + d];
    }

    for (int kt = 0; kt < SEQ/64; kt++) {
        if (kt > qt) {   // fully masked tile: uniform branch, no barrier inside
#pragma unroll
            for (int i = 0; i < 4; i++)
#pragma unroll
                for (int j = 0; j < 4; j++) {
                    const int qg = qt*64 + ty*4 + i;
                    const int kg = kt*64 + tx*4 + j;
                    g_scores[((size_t)bh*SEQ + qg)*SEQ + kg] = -1e30f;
                }
            continue;
        }
        __syncthreads();
        for (int e = tid; e < 64*64; e += 256) {
            int r = e >> 6, d = e & 63;
            Ks[r][d] = g_k[(size_t)(b*SEQ + kt*64 + r) * DIM + h*HD + d];
        }
        __syncthreads();

        float acc[4][4];
#pragma unroll
        for (int i = 0; i < 4; i++)
#pragma unroll
            for (int j = 0; j < 4; j++) acc[i][j] = 0.f;

        for (int d = 0; d < 64; d++) {
            float a[4], bb[4];
#pragma unroll
            for (int i = 0; i < 4; i++) a[i]  = Qs[ty*4 + i][d];
#pragma unroll
            for (int j = 0; j < 4; j++) bb[j] = Ks[tx*4 + j][d];
#pragma unroll
            for (int i = 0; i < 4; i++)
#pragma unroll
                for (int j = 0; j < 4; j++)
                    acc[i][j] = fmaf(a[i], bb[j], acc[i][j]);
        }

#pragma unroll
        for (int i = 0; i < 4; i++)
#pragma unroll
            for (int j = 0; j < 4; j++) {
                const int qg = qt*64 + ty*4 + i;
                const int kg = kt*64 + tx*4 + j;
                g_scores[((size_t)bh*SEQ + qg)*SEQ + kg] =
                    (kg <= qg) ? acc[i][j] * 0.125f : -1e30f;
            }
    }
}

// ---------------- jax-style softmax over each 512-length row ----------------
__global__ __launch_bounds__(128)
void softmax_kernel() {
    __shared__ float red[128];
    float* sr = g_scores + (size_t)blockIdx.x * SEQ;
    const int tid = threadIdx.x;

    float v[4];
    float m = -1e30f;
#pragma unroll
    for (int i = 0; i < 4; i++) { v[i] = sr[tid + 128*i]; m = fmaxf(m, v[i]); }
    red[tid] = m; __syncthreads();
    for (int s = 64; s > 0; s >>= 1) {
        if (tid < s) red[tid] = fmaxf(red[tid], red[tid + s]);
        __syncthreads();
    }
    m = red[0]; __syncthreads();

    float sum = 0.f;
#pragma unroll
    for (int i = 0; i < 4; i++) { v[i] = expf(v[i] - m); sum += v[i]; }
    red[tid] = sum; __syncthreads();
    for (int s = 64; s > 0; s >>= 1) {
        if (tid < s) red[tid] += red[tid + s];
        __syncthreads();
    }
    const float inv = 1.0f / red[0];
#pragma unroll
    for (int i = 0; i < 4; i++) sr[tid + 128*i] = v[i] * inv;
}

// ---------------- out[bh][q][d] = sum_k attn[q][k] * v[k][d] ----------------
__global__ __launch_bounds__(256)
void pv_kernel() {
    __shared__ float Ps[64][65];
    __shared__ float Vs[64][65];
    const int qt = blockIdx.x;
    const int bh = blockIdx.y;
    const int b = bh / NH, h = bh % NH;
    const int tid = threadIdx.x;
    const int ty = tid >> 4, tx = tid & 15;

    float acc[4][4];
#pragma unroll
    for (int i = 0; i < 4; i++)
#pragma unroll
        for (int j = 0; j < 4; j++) acc[i][j] = 0.f;

    for (int kt = 0; kt <= qt; kt++) {   // tiles with kt > qt are exactly zero after softmax
        __syncthreads();
        for (int e = tid; e < 64*64; e += 256) {
            int r = e >> 6, c = e & 63;
            Ps[r][c] = g_scores[((size_t)bh*SEQ + qt*64 + r)*SEQ + kt*64 + c];
            Vs[r][c] = g_v[(size_t)(b*SEQ + kt*64 + r) * DIM + h*HD + c];
        }
        __syncthreads();

        for (int kk = 0; kk < 64; kk++) {
            float p[4], vv[4];
#pragma unroll
            for (int i = 0; i < 4; i++) p[i]  = Ps[ty*4 + i][kk];
#pragma unroll
            for (int j = 0; j < 4; j++) vv[j] = Vs[kk][tx*4 + j];
#pragma unroll
            for (int i = 0; i < 4; i++)
#pragma unroll
                for (int j = 0; j < 4; j++)
                    acc[i][j] = fmaf(p[i], vv[j], acc[i][j]);
        }
    }

#pragma unroll
    for (int i = 0; i < 4; i++)
#pragma unroll
        for (int j = 0; j < 4; j++)
            g_attn[(size_t)(b*SEQ + qt*64 + ty*4 + i) * DIM + h*HD + tx*4 + j] = acc[i][j];
}

// ---------------- launch ----------------
extern "C" void kernel_launch(void* const* d_in, const int* in_sizes, int n_in,
                              void* d_out, int out_size) {
    const float* x  = (const float*)d_in[0];
    const float* Wq = (const float*)d_in[1];
    const float* Wk = (const float*)d_in[2];
    const float* Wv = (const float*)d_in[3];
    const float* Wo = (const float*)d_in[4];
    float* out = (float*)d_out;

    const dim3 blk(32, 8);
    const dim3 gg(DIM/32, MROWS/32);
    gemm_simple<0><<<gg, blk>>>(x, Wq, nullptr);
    gemm_simple<1><<<gg, blk>>>(x, Wk, nullptr);
    gemm_simple<2><<<gg, blk>>>(x, Wv, nullptr);

    rope_tables<<<(SEQ*32)/256, 256>>>();
    rope_apply<<<((size_t)MROWS*NH*32)/256, 256>>>();

    scores_kernel<<<dim3(SEQ/64, BATCH*NH), 256>>>();
    softmax_kernel<<<BATCH*NH*SEQ, 128>>>();
    pv_kernel<<<dim3(SEQ/64, BATCH*NH), 256>>>();

    gemm_simple<3><<<gg, blk>>>(x /*ignored*/, Wo, out);
}

// round 5
// speedup vs baseline: 2.1982x; 2.1982x over previous
#include <cuda_runtime.h>
#include <math.h>

#define BATCH 16
#define SEQ   512
#define DIM   1024
#define NH    16
#define HD    64
#define MROWS (BATCH*SEQ)

// ---------------- scratch (no cudaMalloc allowed) ----------------
__device__ float g_q[(size_t)MROWS*DIM];                 // [b*SEQ+s][h*HD+d]
__device__ float g_k[(size_t)MROWS*DIM];
__device__ float g_v[(size_t)MROWS*DIM];
__device__ float g_attn[(size_t)MROWS*DIM];
__device__ float g_scores[(size_t)BATCH*NH*SEQ*SEQ];     // [bh][q][k], 256 MB
__device__ float g_cos[SEQ][HD];
__device__ float g_sin[SEQ][HD];

// ---------------- C = A @ B^T (fast 128x128 tile, 8x8 per thread) ----------------
// Output-equivalent to gemm_simple (same ascending-k fma order), proven by R2<->R3 invariance.
// MODE 0/1/2: A = Ain (x), C = g_q/g_k/g_v.  MODE 3: A = g_attn, C = Cout.
template<int MODE>
__global__ __launch_bounds__(256, 2)
void sgemm_nt(const float* __restrict__ Ain, const float* __restrict__ Bw,
              float* __restrict__ Cout) {
    const int K = DIM;
    __shared__ float As[8][128];
    __shared__ float Bs[8][128];

    const float* A = (MODE == 3) ? (const float*)g_attn : Ain;
    float* C = (MODE == 0) ? g_q : (MODE == 1) ? g_k : (MODE == 2) ? g_v : Cout;

    const int bm = blockIdx.y * 128;
    const int bn = blockIdx.x * 128;
    const int tid = threadIdx.x;
    const int tx = tid & 15, ty = tid >> 4;

    const int lrow = tid >> 1;          // 128 rows, 2 threads per row
    const int lk   = (tid & 1) << 2;    // k-offset 0 or 4
    const float* Ap = A  + (size_t)(bm + lrow) * K + lk;
    const float* Bp = Bw + (size_t)(bn + lrow) * K + lk;

    float acc[8][8];
#pragma unroll
    for (int i = 0; i < 8; i++)
#pragma unroll
        for (int j = 0; j < 8; j++) acc[i][j] = 0.f;

    for (int kt = 0; kt < K; kt += 8) {
        float4 av = *(const float4*)(Ap + kt);
        float4 bv = *(const float4*)(Bp + kt);
        As[lk+0][lrow] = av.x; As[lk+1][lrow] = av.y;
        As[lk+2][lrow] = av.z; As[lk+3][lrow] = av.w;
        Bs[lk+0][lrow] = bv.x; Bs[lk+1][lrow] = bv.y;
        Bs[lk+2][lrow] = bv.z; Bs[lk+3][lrow] = bv.w;
        __syncthreads();
#pragma unroll
        for (int k = 0; k < 8; k++) {
            float4 a0 = *(const float4*)&As[k][ty*8];
            float4 a1 = *(const float4*)&As[k][ty*8+4];
            float4 b0 = *(const float4*)&Bs[k][tx*8];
            float4 b1 = *(const float4*)&Bs[k][tx*8+4];
            float ar[8] = {a0.x,a0.y,a0.z,a0.w,a1.x,a1.y,a1.z,a1.w};
            float br[8] = {b0.x,b0.y,b0.z,b0.w,b1.x,b1.y,b1.z,b1.w};
#pragma unroll
            for (int i = 0; i < 8; i++)
#pragma unroll
                for (int j = 0; j < 8; j++)
                    acc[i][j] = fmaf(ar[i], br[j], acc[i][j]);
        }
        __syncthreads();
    }

#pragma unroll
    for (int i = 0; i < 8; i++)
#pragma unroll
        for (int j = 0; j < 8; j++)
            C[(size_t)(bm + ty*8 + i) * DIM + (bn + tx*8 + j)] = acc[i][j];
}

// ---------------- literal rope tables (unchanged, verified) ----------------
__global__ void rope_tables() {
    const int idx = blockIdx.x * 256 + threadIdx.x;   // SEQ*32 threads
    const int s = idx >> 5, i = idx & 31;
    const double inv = pow(10000.0, -((double)(2*i)) / 64.0);
    const double f = (double)s * inv;
    const float c = (float)cos(f);
    const float sn = (float)sin(f);
    g_cos[s][i] = c;  g_cos[s][i+32] = c;
    g_sin[s][i] = sn; g_sin[s][i+32] = sn;
}

// ---------------- rope apply (unchanged, verified) ----------------
__global__ void rope_apply() {
    const int idx = blockIdx.x * 256 + threadIdx.x;   // MROWS*NH*32 threads
    const int i = idx & 31;
    const int h = (idx >> 5) & 15;
    const int m = idx >> 9;            // b*SEQ + s
    const int s = m & (SEQ-1);
    const float c  = g_cos[s][i];
    const float sn = g_sin[s][i];
    const size_t base = (size_t)m * DIM + h*HD + i;
    float x1 = g_q[base], x2 = g_q[base + 32];
    g_q[base]      = x1*c - x2*sn;
    g_q[base + 32] = x2*c + x1*sn;
    x1 = g_k[base]; x2 = g_k[base + 32];
    g_k[base]      = x1*c - x2*sn;
    g_k[base + 32] = x2*c + x1*sn;
}

// ---------------- scores (unchanged, verified) ----------------
__global__ __launch_bounds__(256)
void scores_kernel() {
    __shared__ float Qs[64][65];
    __shared__ float Ks[64][65];
    const int qt = blockIdx.x;
    const int bh = blockIdx.y;
    const int b = bh / NH, h = bh % NH;
    const int tid = threadIdx.x;
    const int ty = tid >> 4, tx = tid & 15;

    for (int e = tid; e < 64*64; e += 256) {
        int r = e >> 6, d = e & 63;
        Qs[r][d] = g_q[(size_t)(b*SEQ + qt*64 + r) * DIM + h*HD + d];
    }

    for (int kt = 0; kt < SEQ/64; kt++) {
        if (kt > qt) {
#pragma unroll
            for (int i = 0; i < 4; i++)
#pragma unroll
                for (int j = 0; j < 4; j++) {
                    const int qg = qt*64 + ty*4 + i;
                    const int kg = kt*64 + tx*4 + j;
                    g_scores[((size_t)bh*SEQ + qg)*SEQ + kg] = -1e30f;
                }
            continue;
        }
        __syncthreads();
        for (int e = tid; e < 64*64; e += 256) {
            int r = e >> 6, d = e & 63;
            Ks[r][d] = g_k[(size_t)(b*SEQ + kt*64 + r) * DIM + h*HD + d];
        }
        __syncthreads();

        float acc[4][4];
#pragma unroll
        for (int i = 0; i < 4; i++)
#pragma unroll
            for (int j = 0; j < 4; j++) acc[i][j] = 0.f;

        for (int d = 0; d < 64; d++) {
            float a[4], bb[4];
#pragma unroll
            for (int i = 0; i < 4; i++) a[i]  = Qs[ty*4 + i][d];
#pragma unroll
            for (int j = 0; j < 4; j++) bb[j] = Ks[tx*4 + j][d];
#pragma unroll
            for (int i = 0; i < 4; i++)
#pragma unroll
                for (int j = 0; j < 4; j++)
                    acc[i][j] = fmaf(a[i], bb[j], acc[i][j]);
        }

#pragma unroll
        for (int i = 0; i < 4; i++)
#pragma unroll
            for (int j = 0; j < 4; j++) {
                const int qg = qt*64 + ty*4 + i;
                const int kg = kt*64 + tx*4 + j;
                g_scores[((size_t)bh*SEQ + qg)*SEQ + kg] =
                    (kg <= qg) ? acc[i][j] * 0.125f : -1e30f;
            }
    }
}

// ---------------- softmax (unchanged, verified) ----------------
__global__ __launch_bounds__(128)
void softmax_kernel() {
    __shared__ float red[128];
    float* sr = g_scores + (size_t)blockIdx.x * SEQ;
    const int tid = threadIdx.x;

    float v[4];
    float m = -1e30f;
#pragma unroll
    for (int i = 0; i < 4; i++) { v[i] = sr[tid + 128*i]; m = fmaxf(m, v[i]); }
    red[tid] = m; __syncthreads();
    for (int s = 64; s > 0; s >>= 1) {
        if (tid < s) red[tid] = fmaxf(red[tid], red[tid + s]);
        __syncthreads();
    }
    m = red[0]; __syncthreads();

    float sum = 0.f;
#pragma unroll
    for (int i = 0; i < 4; i++) { v[i] = expf(v[i] - m); sum += v[i]; }
    red[tid] = sum; __syncthreads();
    for (int s = 64; s > 0; s >>= 1) {
        if (tid < s) red[tid] += red[tid + s];
        __syncthreads();
    }
    const float inv = 1.0f / red[0];
#pragma unroll
    for (int i = 0; i < 4; i++) sr[tid + 128*i] = v[i] * inv;
}

// ---------------- P @ V (unchanged, verified) ----------------
__global__ __launch_bounds__(256)
void pv_kernel() {
    __shared__ float Ps[64][65];
    __shared__ float Vs[64][65];
    const int qt = blockIdx.x;
    const int bh = blockIdx.y;
    const int b = bh / NH, h = bh % NH;
    const int tid = threadIdx.x;
    const int ty = tid >> 4, tx = tid & 15;

    float acc[4][4];
#pragma unroll
    for (int i = 0; i < 4; i++)
#pragma unroll
        for (int j = 0; j < 4; j++) acc[i][j] = 0.f;

    for (int kt = 0; kt <= qt; kt++) {
        __syncthreads();
        for (int e = tid; e < 64*64; e += 256) {
            int r = e >> 6, c = e & 63;
            Ps[r][c] = g_scores[((size_t)bh*SEQ + qt*64 + r)*SEQ + kt*64 + c];
            Vs[r][c] = g_v[(size_t)(b*SEQ + kt*64 + r) * DIM + h*HD + c];
        }
        __syncthreads();

        for (int kk = 0; kk < 64; kk++) {
            float p[4], vv[4];
#pragma unroll
            for (int i = 0; i < 4; i++) p[i]  = Ps[ty*4 + i][kk];
#pragma unroll
            for (int j = 0; j < 4; j++) vv[j] = Vs[kk][tx*4 + j];
#pragma unroll
            for (int i = 0; i < 4; i++)
#pragma unroll
                for (int j = 0; j < 4; j++)
                    acc[i][j] = fmaf(p[i], vv[j], acc[i][j]);
        }
    }

#pragma unroll
    for (int i = 0; i < 4; i++)
#pragma unroll
        for (int j = 0; j < 4; j++)
            g_attn[(size_t)(b*SEQ + qt*64 + ty*4 + i) * DIM + h*HD + tx*4 + j] = acc[i][j];
}

// ---------------- launch ----------------
extern "C" void kernel_launch(void* const* d_in, const int* in_sizes, int n_in,
                              void* d_out, int out_size) {
    const float* x  = (const float*)d_in[0];
    const float* Wq = (const float*)d_in[1];
    const float* Wk = (const float*)d_in[2];
    const float* Wv = (const float*)d_in[3];
    const float* Wo = (const float*)d_in[4];
    float* out = (float*)d_out;

    const dim3 gg(DIM/128, MROWS/128);   // (8, 64)
    sgemm_nt<0><<<gg, 256>>>(x, Wq, nullptr);
    sgemm_nt<1><<<gg, 256>>>(x, Wk, nullptr);
    sgemm_nt<2><<<gg, 256>>>(x, Wv, nullptr);

    rope_tables<<<(SEQ*32)/256, 256>>>();
    rope_apply<<<((size_t)MROWS*NH*32)/256, 256>>>();

    scores_kernel<<<dim3(SEQ/64, BATCH*NH), 256>>>();
    softmax_kernel<<<BATCH*NH*SEQ, 128>>>();
    pv_kernel<<<dim3(SEQ/64, BATCH*NH), 256>>>();

    sgemm_nt<3><<<gg, 256>>>(x /*ignored*/, Wo, out);
}

// round 6
// speedup vs baseline: 2.3419x; 1.0653x over previous
#include <cuda_runtime.h>
#include <math.h>

#define BATCH 16
#define SEQ   512
#define DIM   1024
#define NH    16
#define HD    64
#define MROWS (BATCH*SEQ)

// ---------------- scratch (no cudaMalloc allowed) ----------------
__device__ float g_q[(size_t)MROWS*DIM];                 // [b*SEQ+s][h*HD+d]
__device__ float g_k[(size_t)MROWS*DIM];
__device__ float g_v[(size_t)MROWS*DIM];
__device__ float g_attn[(size_t)MROWS*DIM];
__device__ float g_cos[SEQ][HD];
__device__ float g_sin[SEQ][HD];

// ---------------- C = A @ B^T (fast 128x128 tile, 8x8 per thread — verified R5) ----------------
template<int MODE>
__global__ __launch_bounds__(256, 2)
void sgemm_nt(const float* __restrict__ Ain, const float* __restrict__ Bw,
              float* __restrict__ Cout) {
    const int K = DIM;
    __shared__ float As[8][128];
    __shared__ float Bs[8][128];

    const float* A = (MODE == 3) ? (const float*)g_attn : Ain;
    float* C = (MODE == 0) ? g_q : (MODE == 1) ? g_k : (MODE == 2) ? g_v : Cout;

    const int bm = blockIdx.y * 128;
    const int bn = blockIdx.x * 128;
    const int tid = threadIdx.x;
    const int tx = tid & 15, ty = tid >> 4;

    const int lrow = tid >> 1;
    const int lk   = (tid & 1) << 2;
    const float* Ap = A  + (size_t)(bm + lrow) * K + lk;
    const float* Bp = Bw + (size_t)(bn + lrow) * K + lk;

    float acc[8][8];
#pragma unroll
    for (int i = 0; i < 8; i++)
#pragma unroll
        for (int j = 0; j < 8; j++) acc[i][j] = 0.f;

    for (int kt = 0; kt < K; kt += 8) {
        float4 av = *(const float4*)(Ap + kt);
        float4 bv = *(const float4*)(Bp + kt);
        As[lk+0][lrow] = av.x; As[lk+1][lrow] = av.y;
        As[lk+2][lrow] = av.z; As[lk+3][lrow] = av.w;
        Bs[lk+0][lrow] = bv.x; Bs[lk+1][lrow] = bv.y;
        Bs[lk+2][lrow] = bv.z; Bs[lk+3][lrow] = bv.w;
        __syncthreads();
#pragma unroll
        for (int k = 0; k < 8; k++) {
            float4 a0 = *(const float4*)&As[k][ty*8];
            float4 a1 = *(const float4*)&As[k][ty*8+4];
            float4 b0 = *(const float4*)&Bs[k][tx*8];
            float4 b1 = *(const float4*)&Bs[k][tx*8+4];
            float ar[8] = {a0.x,a0.y,a0.z,a0.w,a1.x,a1.y,a1.z,a1.w};
            float br[8] = {b0.x,b0.y,b0.z,b0.w,b1.x,b1.y,b1.z,b1.w};
#pragma unroll
            for (int i = 0; i < 8; i++)
#pragma unroll
                for (int j = 0; j < 8; j++)
                    acc[i][j] = fmaf(ar[i], br[j], acc[i][j]);
        }
        __syncthreads();
    }

#pragma unroll
    for (int i = 0; i < 8; i++)
#pragma unroll
        for (int j = 0; j < 8; j++)
            C[(size_t)(bm + ty*8 + i) * DIM + (bn + tx*8 + j)] = acc[i][j];
}

// ---------------- rope tables (verified) ----------------
__global__ void rope_tables() {
    const int idx = blockIdx.x * 256 + threadIdx.x;
    const int s = idx >> 5, i = idx & 31;
    const double inv = pow(10000.0, -((double)(2*i)) / 64.0);
    const double f = (double)s * inv;
    const float c = (float)cos(f);
    const float sn = (float)sin(f);
    g_cos[s][i] = c;  g_cos[s][i+32] = c;
    g_sin[s][i] = sn; g_sin[s][i+32] = sn;
}

// ---------------- rope apply (verified) ----------------
__global__ void rope_apply() {
    const int idx = blockIdx.x * 256 + threadIdx.x;
    const int i = idx & 31;
    const int h = (idx >> 5) & 15;
    const int m = idx >> 9;
    const int s = m & (SEQ-1);
    const float c  = g_cos[s][i];
    const float sn = g_sin[s][i];
    const size_t base = (size_t)m * DIM + h*HD + i;
    float x1 = g_q[base], x2 = g_q[base + 32];
    g_q[base]      = x1*c - x2*sn;
    g_q[base + 32] = x2*c + x1*sn;
    x1 = g_k[base]; x2 = g_k[base + 32];
    g_k[base]      = x1*c - x2*sn;
    g_k[base + 32] = x2*c + x1*sn;
}

// ---------------- fused flash attention: scores+softmax+PV in one pass ----------------
// Same tiling/indexing as the verified scores_kernel/pv_kernel; online softmax added.
// grid (SEQ/64, BATCH*NH), 256 threads; thread owns q-rows ty*4+i, and for S: k-cols tx*4+j,
// for O: d-cols tx*4+j. Row reductions via width-16 xor shuffles (lanes with equal ty).
__global__ __launch_bounds__(256)
void flash_kernel() {
    extern __shared__ float sm[];
    float (*Qs)[65]  = (float(*)[65])sm;             // [64][65]
    float (*KVs)[65] = (float(*)[65])(sm + 64*65);   // K tile, then reused for V
    float (*Ps)[65]  = (float(*)[65])(sm + 2*64*65); // staged exp-weights

    const int qt = blockIdx.x;
    const int bh = blockIdx.y;
    const int b = bh / NH, h = bh % NH;
    const int tid = threadIdx.x;
    const int ty = tid >> 4, tx = tid & 15;

    for (int e = tid; e < 64*64; e += 256) {
        int r = e >> 6, d = e & 63;
        Qs[r][d] = g_q[(size_t)(b*SEQ + qt*64 + r) * DIM + h*HD + d];
    }

    float mrow[4], lrow[4], O[4][4];
#pragma unroll
    for (int i = 0; i < 4; i++) {
        mrow[i] = -1e30f; lrow[i] = 0.f;
#pragma unroll
        for (int j = 0; j < 4; j++) O[i][j] = 0.f;
    }

    for (int kt = 0; kt <= qt; kt++) {
        __syncthreads();   // prev PV reads of KVs/Ps done; first iter: Qs visible
        for (int e = tid; e < 64*64; e += 256) {
            int r = e >> 6, d = e & 63;
            KVs[r][d] = g_k[(size_t)(b*SEQ + kt*64 + r) * DIM + h*HD + d];
        }
        __syncthreads();

        // S = (Q @ K^T) * 0.125, causal mask on diagonal tile
        float s[4][4];
#pragma unroll
        for (int i = 0; i < 4; i++)
#pragma unroll
            for (int j = 0; j < 4; j++) s[i][j] = 0.f;
        for (int d = 0; d < 64; d++) {
            float a[4], bb[4];
#pragma unroll
            for (int i = 0; i < 4; i++) a[i]  = Qs[ty*4 + i][d];
#pragma unroll
            for (int j = 0; j < 4; j++) bb[j] = KVs[tx*4 + j][d];
#pragma unroll
            for (int i = 0; i < 4; i++)
#pragma unroll
                for (int j = 0; j < 4; j++)
                    s[i][j] = fmaf(a[i], bb[j], s[i][j]);
        }
        const bool diag = (kt == qt);
#pragma unroll
        for (int i = 0; i < 4; i++)
#pragma unroll
            for (int j = 0; j < 4; j++) {
                s[i][j] *= 0.125f;
                if (diag && (tx*4 + j > ty*4 + i)) s[i][j] = -1e30f;
            }

        // online softmax per q-row (reduce over 16 tx lanes, width-16 butterflies)
#pragma unroll
        for (int i = 0; i < 4; i++) {
            float tm = fmaxf(fmaxf(s[i][0], s[i][1]), fmaxf(s[i][2], s[i][3]));
#pragma unroll
            for (int off = 8; off >= 1; off >>= 1)
                tm = fmaxf(tm, __shfl_xor_sync(0xffffffffu, tm, off, 16));
            const float mn = fmaxf(mrow[i], tm);
            const float alpha = __expf(mrow[i] - mn);
            float rs = 0.f;
#pragma unroll
            for (int j = 0; j < 4; j++) {
                s[i][j] = __expf(s[i][j] - mn);
                rs += s[i][j];
            }
#pragma unroll
            for (int off = 8; off >= 1; off >>= 1)
                rs += __shfl_xor_sync(0xffffffffu, rs, off, 16);
            lrow[i] = lrow[i] * alpha + rs;
            mrow[i] = mn;
#pragma unroll
            for (int j = 0; j < 4; j++) O[i][j] *= alpha;
        }

        __syncthreads();   // all lanes done reading KVs as K
        for (int e = tid; e < 64*64; e += 256) {
            int r = e >> 6, c = e & 63;
            KVs[r][c] = g_v[(size_t)(b*SEQ + kt*64 + r) * DIM + h*HD + c];
        }
#pragma unroll
        for (int i = 0; i < 4; i++)
#pragma unroll
            for (int j = 0; j < 4; j++)
                Ps[ty*4 + i][tx*4 + j] = s[i][j];
        __syncthreads();

        // O += P @ V   (identical loop structure to verified pv_kernel)
        for (int kk = 0; kk < 64; kk++) {
            float p[4], vv[4];
#pragma unroll
            for (int i = 0; i < 4; i++) p[i]  = Ps[ty*4 + i][kk];
#pragma unroll
            for (int j = 0; j < 4; j++) vv[j] = KVs[kk][tx*4 + j];
#pragma unroll
            for (int i = 0; i < 4; i++)
#pragma unroll
                for (int j = 0; j < 4; j++)
                    O[i][j] = fmaf(p[i], vv[j], O[i][j]);
        }
    }

#pragma unroll
    for (int i = 0; i < 4; i++) {
        const float inv = 1.0f / lrow[i];
#pragma unroll
        for (int j = 0; j < 4; j++)
            g_attn[(size_t)(b*SEQ + qt*64 + ty*4 + i) * DIM + h*HD + tx*4 + j] = O[i][j] * inv;
    }
}

// ---------------- launch ----------------
extern "C" void kernel_launch(void* const* d_in, const int* in_sizes, int n_in,
                              void* d_out, int out_size) {
    const float* x  = (const float*)d_in[0];
    const float* Wq = (const float*)d_in[1];
    const float* Wk = (const float*)d_in[2];
    const float* Wv = (const float*)d_in[3];
    const float* Wo = (const float*)d_in[4];
    float* out = (float*)d_out;

    const dim3 gg(DIM/128, MROWS/128);
    sgemm_nt<0><<<gg, 256>>>(x, Wq, nullptr);
    sgemm_nt<1><<<gg, 256>>>(x, Wk, nullptr);
    sgemm_nt<2><<<gg, 256>>>(x, Wv, nullptr);

    rope_tables<<<(SEQ*32)/256, 256>>>();
    rope_apply<<<((size_t)MROWS*NH*32)/256, 256>>>();

    const int smem = 3 * 64 * 65 * sizeof(float);   // 49,920 B
    cudaFuncSetAttribute(flash_kernel, cudaFuncAttributeMaxDynamicSharedMemorySize, smem);
    flash_kernel<<<dim3(SEQ/64, BATCH*NH), 256, smem>>>();

    sgemm_nt<3><<<gg, 256>>>(x /*ignored*/, Wo, out);
}

// round 9
// speedup vs baseline: 4.5112x; 1.9263x over previous
#include <cuda_runtime.h>
#include <cuda_bf16.h>
#include <math.h>
#include <stdint.h>

#define BATCH 16
#define SEQ   512
#define DIM   1024
#define NH    16
#define HD    64
#define MROWS (BATCH*SEQ)

// ---------------- scratch (no cudaMalloc allowed) ----------------
__device__ float g_q[(size_t)MROWS*DIM];
__device__ float g_k[(size_t)MROWS*DIM];
__device__ float g_v[(size_t)MROWS*DIM];
__device__ float g_attn[(size_t)MROWS*DIM];
__device__ float g_cos[SEQ][HD];
__device__ float g_sin[SEQ][HD];
__device__ __nv_bfloat16 g_xh[(size_t)MROWS*DIM];
__device__ __nv_bfloat16 g_xl[(size_t)MROWS*DIM];
__device__ __nv_bfloat16 g_ath[(size_t)MROWS*DIM];
__device__ __nv_bfloat16 g_atl[(size_t)MROWS*DIM];
__device__ __nv_bfloat16 g_wh[4][(size_t)DIM*DIM];
__device__ __nv_bfloat16 g_wl[4][(size_t)DIM*DIM];

// ---------------- helpers ----------------
__device__ __forceinline__ uint32_t smem_u32(const void* p) {
    uint32_t a;
    asm("{ .reg .u64 t; cvta.to.shared.u64 t, %1; cvt.u32.u64 %0, t; }" : "=r"(a) : "l"(p));
    return a;
}
__device__ __forceinline__ void ldsm_x4(uint32_t* r, uint32_t addr) {
    asm volatile("ldmatrix.sync.aligned.m8n8.x4.shared.b16 {%0,%1,%2,%3}, [%4];"
                 : "=r"(r[0]), "=r"(r[1]), "=r"(r[2]), "=r"(r[3]) : "r"(addr));
}
// NON-trans: [n][k] row-major storage IS the col-major KxN fragment layout.
__device__ __forceinline__ void ldsm_x2(uint32_t* r, uint32_t addr) {
    asm volatile("ldmatrix.sync.aligned.m8n8.x2.shared.b16 {%0,%1}, [%2];"
                 : "=r"(r[0]), "=r"(r[1]) : "r"(addr));
}
__device__ __forceinline__ void mma_bf16(float* c, const uint32_t* a, const uint32_t* b) {
    asm volatile("mma.sync.aligned.m16n8k16.row.col.f32.bf16.bf16.f32 "
                 "{%0,%1,%2,%3}, {%4,%5,%6,%7}, {%8,%9}, {%0,%1,%2,%3};"
                 : "+f"(c[0]), "+f"(c[1]), "+f"(c[2]), "+f"(c[3])
                 : "r"(a[0]), "r"(a[1]), "r"(a[2]), "r"(a[3]), "r"(b[0]), "r"(b[1]));
}

// ---------------- split fp32 -> bf16 hi + bf16 lo ----------------
template<int MODE>
__global__ void conv_split(const float* __restrict__ src, int n) {
    const int i = blockIdx.x * 256 + threadIdx.x;
    if (i >= n) return;
    const float v = (MODE == 5) ? g_attn[i] : src[i];
    const __nv_bfloat16 h = __float2bfloat16(v);
    const __nv_bfloat16 l = __float2bfloat16(v - __bfloat162float(h));
    if (MODE == 0)      { g_xh[i] = h;  g_xl[i] = l; }
    else if (MODE == 5) { g_ath[i] = h; g_atl[i] = l; }
    else                { g_wh[MODE-1][i] = h; g_wl[MODE-1][i] = l; }
}

// ---------------- split-bf16 tensor-core GEMM: C = A @ W^T ----------------
#define KC   32
#define LDS  40
template<int MODE>
__global__ __launch_bounds__(256, 2)
void bgemm_mma(float* __restrict__ Cout) {
    __shared__ __nv_bfloat16 sAh[128][LDS], sAl[128][LDS];
    __shared__ __nv_bfloat16 sBh[128][LDS], sBl[128][LDS];

    const __nv_bfloat16* __restrict__ Ah = (MODE == 3) ? g_ath : g_xh;
    const __nv_bfloat16* __restrict__ Al = (MODE == 3) ? g_atl : g_xl;
    const __nv_bfloat16* __restrict__ Bh = g_wh[MODE];
    const __nv_bfloat16* __restrict__ Bl = g_wl[MODE];
    float* C = (MODE == 0) ? g_q : (MODE == 1) ? g_k : (MODE == 2) ? g_v : Cout;

    const int bm = blockIdx.y * 128, bn = blockIdx.x * 128;
    const int tid = threadIdx.x, wid = tid >> 5, lane = tid & 31;
    const int wm = (wid & 1) * 64;
    const int wn = (wid >> 1) * 32;

    float acc[4][4][4];
#pragma unroll
    for (int i = 0; i < 4; i++)
#pragma unroll
        for (int j = 0; j < 4; j++)
#pragma unroll
            for (int r = 0; r < 4; r++) acc[i][j][r] = 0.f;

    const int a_row = lane & 15, a_koff = (lane >> 4) * 8;          // ldmatrix.x4 (A)
    const int b_row = lane & 7,  b_koff = ((lane >> 3) & 1) * 8;    // ldmatrix.x2 (B), lanes 0-15

    for (int kc = 0; kc < DIM / KC; kc++) {
        __syncthreads();
#pragma unroll
        for (int e = tid; e < 512; e += 256) {
            const int r = e >> 2, c8 = (e & 3) * 8;
            const size_t ga = (size_t)(bm + r) * DIM + kc * KC + c8;
            const size_t gb = (size_t)(bn + r) * DIM + kc * KC + c8;
            *(uint4*)&sAh[r][c8] = *(const uint4*)(Ah + ga);
            *(uint4*)&sAl[r][c8] = *(const uint4*)(Al + ga);
            *(uint4*)&sBh[r][c8] = *(const uint4*)(Bh + gb);
            *(uint4*)&sBl[r][c8] = *(const uint4*)(Bl + gb);
        }
        __syncthreads();

#pragma unroll
        for (int ks = 0; ks < KC / 16; ks++) {
            const int k0 = ks * 16;
            uint32_t afr[4][4], bfr[4][2];

            // term 1: Ah * Bh
#pragma unroll
            for (int im = 0; im < 4; im++)
                ldsm_x4(afr[im], smem_u32(&sAh[wm + im*16 + a_row][k0 + a_koff]));
#pragma unroll
            for (int in = 0; in < 4; in++)
                ldsm_x2(bfr[in], smem_u32(&sBh[wn + in*8 + b_row][k0 + b_koff]));
#pragma unroll
            for (int im = 0; im < 4; im++)
#pragma unroll
                for (int in = 0; in < 4; in++)
                    mma_bf16(acc[im][in], afr[im], bfr[in]);

            // term 2: Ah * Bl (A frags still live)
#pragma unroll
            for (int in = 0; in < 4; in++)
                ldsm_x2(bfr[in], smem_u32(&sBl[wn + in*8 + b_row][k0 + b_koff]));
#pragma unroll
            for (int im = 0; im < 4; im++)
#pragma unroll
                for (int in = 0; in < 4; in++)
                    mma_bf16(acc[im][in], afr[im], bfr[in]);

            // term 3: Al * Bh
#pragma unroll
            for (int im = 0; im < 4; im++)
                ldsm_x4(afr[im], smem_u32(&sAl[wm + im*16 + a_row][k0 + a_koff]));
#pragma unroll
            for (int in = 0; in < 4; in++)
                ldsm_x2(bfr[in], smem_u32(&sBh[wn + in*8 + b_row][k0 + b_koff]));
#pragma unroll
            for (int im = 0; im < 4; im++)
#pragma unroll
                for (int in = 0; in < 4; in++)
                    mma_bf16(acc[im][in], afr[im], bfr[in]);
        }
    }

    const int er = lane >> 2, ec = (lane & 3) * 2;
#pragma unroll
    for (int im = 0; im < 4; im++)
#pragma unroll
        for (int in = 0; in < 4; in++) {
            const size_t r0 = (size_t)(bm + wm + im*16 + er) * DIM + (bn + wn + in*8 + ec);
            const size_t r1 = r0 + 8 * DIM;
            C[r0]     = acc[im][in][0];
            C[r0 + 1] = acc[im][in][1];
            C[r1]     = acc[im][in][2];
            C[r1 + 1] = acc[im][in][3];
        }
}

// ---------------- rope tables (verified) ----------------
__global__ void rope_tables() {
    const int idx = blockIdx.x * 256 + threadIdx.x;
    const int s = idx >> 5, i = idx & 31;
    const double inv = pow(10000.0, -((double)(2*i)) / 64.0);
    const double f = (double)s * inv;
    g_cos[s][i] = (float)cos(f);  g_cos[s][i+32] = (float)cos(f);
    g_sin[s][i] = (float)sin(f);  g_sin[s][i+32] = (float)sin(f);
}

// ---------------- rope apply (verified) ----------------
__global__ void rope_apply() {
    const int idx = blockIdx.x * 256 + threadIdx.x;
    const int i = idx & 31;
    const int h = (idx >> 5) & 15;
    const int m = idx >> 9;
    const int s = m & (SEQ-1);
    const float c  = g_cos[s][i];
    const float sn = g_sin[s][i];
    const size_t base = (size_t)m * DIM + h*HD + i;
    float x1 = g_q[base], x2 = g_q[base + 32];
    g_q[base]      = x1*c - x2*sn;
    g_q[base + 32] = x2*c + x1*sn;
    x1 = g_k[base]; x2 = g_k[base + 32];
    g_k[base]      = x1*c - x2*sn;
    g_k[base + 32] = x2*c + x1*sn;
}

// ---------------- fused flash attention (verified R6, unchanged) ----------------
__global__ __launch_bounds__(256)
void flash_kernel() {
    extern __shared__ float smf[];
    float (*Qs)[65]  = (float(*)[65])smf;
    float (*KVs)[65] = (float(*)[65])(smf + 64*65);
    float (*Ps)[65]  = (float(*)[65])(smf + 2*64*65);

    const int qt = blockIdx.x;
    const int bh = blockIdx.y;
    const int b = bh / NH, h = bh % NH;
    const int tid = threadIdx.x;
    const int ty = tid >> 4, tx = tid & 15;

    for (int e = tid; e < 64*64; e += 256) {
        int r = e >> 6, d = e & 63;
        Qs[r][d] = g_q[(size_t)(b*SEQ + qt*64 + r) * DIM + h*HD + d];
    }

    float mrow[4], lrow[4], O[4][4];
#pragma unroll
    for (int i = 0; i < 4; i++) {
        mrow[i] = -1e30f; lrow[i] = 0.f;
#pragma unroll
        for (int j = 0; j < 4; j++) O[i][j] = 0.f;
    }

    for (int kt = 0; kt <= qt; kt++) {
        __syncthreads();
        for (int e = tid; e < 64*64; e += 256) {
            int r = e >> 6, d = e & 63;
            KVs[r][d] = g_k[(size_t)(b*SEQ + kt*64 + r) * DIM + h*HD + d];
        }
        __syncthreads();

        float s[4][4];
#pragma unroll
        for (int i = 0; i < 4; i++)
#pragma unroll
            for (int j = 0; j < 4; j++) s[i][j] = 0.f;
        for (int d = 0; d < 64; d++) {
            float a[4], bb[4];
#pragma unroll
            for (int i = 0; i < 4; i++) a[i]  = Qs[ty*4 + i][d];
#pragma unroll
            for (int j = 0; j < 4; j++) bb[j] = KVs[tx*4 + j][d];
#pragma unroll
            for (int i = 0; i < 4; i++)
#pragma unroll
                for (int j = 0; j < 4; j++)
                    s[i][j] = fmaf(a[i], bb[j], s[i][j]);
        }
        const bool diag = (kt == qt);
#pragma unroll
        for (int i = 0; i < 4; i++)
#pragma unroll
            for (int j = 0; j < 4; j++) {
                s[i][j] *= 0.125f;
                if (diag && (tx*4 + j > ty*4 + i)) s[i][j] = -1e30f;
            }

#pragma unroll
        for (int i = 0; i < 4; i++) {
            float tm = fmaxf(fmaxf(s[i][0], s[i][1]), fmaxf(s[i][2], s[i][3]));
#pragma unroll
            for (int off = 8; off >= 1; off >>= 1)
                tm = fmaxf(tm, __shfl_xor_sync(0xffffffffu, tm, off, 16));
            const float mn = fmaxf(mrow[i], tm);
            const float alpha = __expf(mrow[i] - mn);
            float rs = 0.f;
#pragma unroll
            for (int j = 0; j < 4; j++) {
                s[i][j] = __expf(s[i][j] - mn);
                rs += s[i][j];
            }
#pragma unroll
            for (int off = 8; off >= 1; off >>= 1)
                rs += __shfl_xor_sync(0xffffffffu, rs, off, 16);
            lrow[i] = lrow[i] * alpha + rs;
            mrow[i] = mn;
#pragma unroll
            for (int j = 0; j < 4; j++) O[i][j] *= alpha;
        }

        __syncthreads();
        for (int e = tid; e < 64*64; e += 256) {
            int r = e >> 6, c = e & 63;
            KVs[r][c] = g_v[(size_t)(b*SEQ + kt*64 + r) * DIM + h*HD + c];
        }
#pragma unroll
        for (int i = 0; i < 4; i++)
#pragma unroll
            for (int j = 0; j < 4; j++)
                Ps[ty*4 + i][tx*4 + j] = s[i][j];
        __syncthreads();

        for (int kk = 0; kk < 64; kk++) {
            float p[4], vv[4];
#pragma unroll
            for (int i = 0; i < 4; i++) p[i]  = Ps[ty*4 + i][kk];
#pragma unroll
            for (int j = 0; j < 4; j++) vv[j] = KVs[kk][tx*4 + j];
#pragma unroll
            for (int i = 0; i < 4; i++)
#pragma unroll
                for (int j = 0; j < 4; j++)
                    O[i][j] = fmaf(p[i], vv[j], O[i][j]);
        }
    }

#pragma unroll
    for (int i = 0; i < 4; i++) {
        const float inv = 1.0f / lrow[i];
#pragma unroll
        for (int j = 0; j < 4; j++)
            g_attn[(size_t)(b*SEQ + qt*64 + ty*4 + i) * DIM + h*HD + tx*4 + j] = O[i][j] * inv;
    }
}

// ---------------- launch ----------------
extern "C" void kernel_launch(void* const* d_in, const int* in_sizes, int n_in,
                              void* d_out, int out_size) {
    const float* x  = (const float*)d_in[0];
    const float* Wq = (const float*)d_in[1];
    const float* Wk = (const float*)d_in[2];
    const float* Wv = (const float*)d_in[3];
    const float* Wo = (const float*)d_in[4];
    float* out = (float*)d_out;

    const int NX = MROWS * DIM;
    const int NW = DIM * DIM;

    conv_split<0><<<(NX + 255)/256, 256>>>(x,  NX);
    conv_split<1><<<(NW + 255)/256, 256>>>(Wq, NW);
    conv_split<2><<<(NW + 255)/256, 256>>>(Wk, NW);
    conv_split<3><<<(NW + 255)/256, 256>>>(Wv, NW);
    conv_split<4><<<(NW + 255)/256, 256>>>(Wo, NW);

    const dim3 gg(DIM/128, MROWS/128);   // (8, 64)
    bgemm_mma<0><<<gg, 256>>>(nullptr);
    bgemm_mma<1><<<gg, 256>>>(nullptr);
    bgemm_mma<2><<<gg, 256>>>(nullptr);

    rope_tables<<<(SEQ*32)/256, 256>>>();
    rope_apply<<<((size_t)MROWS*NH*32)/256, 256>>>();

    const int fsmem = 3 * 64 * 65 * sizeof(float);
    cudaFuncSetAttribute(flash_kernel, cudaFuncAttributeMaxDynamicSharedMemorySize, fsmem);
    flash_kernel<<<dim3(SEQ/64, BATCH*NH), 256, fsmem>>>();

    conv_split<5><<<(NX + 255)/256, 256>>>(nullptr, NX);
    bgemm_mma<3><<<gg, 256>>>(out);
}

// round 10
// speedup vs baseline: 4.8889x; 1.0837x over previous
#include <cuda_runtime.h>
#include <cuda_bf16.h>
#include <math.h>
#include <stdint.h>

#define BATCH 16
#define SEQ   512
#define DIM   1024
#define NH    16
#define HD    64
#define MROWS (BATCH*SEQ)

// ---------------- scratch (no cudaMalloc allowed) ----------------
__device__ float g_q[(size_t)MROWS*DIM];
__device__ float g_k[(size_t)MROWS*DIM];
__device__ float g_v[(size_t)MROWS*DIM];
__device__ float g_cos[SEQ][HD];
__device__ float g_sin[SEQ][HD];
__device__ __nv_bfloat16 g_xh[(size_t)MROWS*DIM];
__device__ __nv_bfloat16 g_xl[(size_t)MROWS*DIM];
__device__ __nv_bfloat16 g_ath[(size_t)MROWS*DIM];
__device__ __nv_bfloat16 g_atl[(size_t)MROWS*DIM];
__device__ __nv_bfloat16 g_wh[4][(size_t)DIM*DIM];
__device__ __nv_bfloat16 g_wl[4][(size_t)DIM*DIM];

// ---------------- helpers ----------------
__device__ __forceinline__ uint32_t smem_u32(const void* p) {
    uint32_t a;
    asm("{ .reg .u64 t; cvta.to.shared.u64 t, %1; cvt.u32.u64 %0, t; }" : "=r"(a) : "l"(p));
    return a;
}
__device__ __forceinline__ void ldsm_x4(uint32_t* r, uint32_t addr) {
    asm volatile("ldmatrix.sync.aligned.m8n8.x4.shared.b16 {%0,%1,%2,%3}, [%4];"
                 : "=r"(r[0]), "=r"(r[1]), "=r"(r[2]), "=r"(r[3]) : "r"(addr));
}
__device__ __forceinline__ void ldsm_x2(uint32_t* r, uint32_t addr) {
    asm volatile("ldmatrix.sync.aligned.m8n8.x2.shared.b16 {%0,%1}, [%2];"
                 : "=r"(r[0]), "=r"(r[1]) : "r"(addr));
}
__device__ __forceinline__ void mma_bf16(float* c, const uint32_t* a, const uint32_t* b) {
    asm volatile("mma.sync.aligned.m16n8k16.row.col.f32.bf16.bf16.f32 "
                 "{%0,%1,%2,%3}, {%4,%5,%6,%7}, {%8,%9}, {%0,%1,%2,%3};"
                 : "+f"(c[0]), "+f"(c[1]), "+f"(c[2]), "+f"(c[3])
                 : "r"(a[0]), "r"(a[1]), "r"(a[2]), "r"(a[3]), "r"(b[0]), "r"(b[1]));
}
__device__ __forceinline__ void cp_async16(uint32_t dst, const void* src) {
    asm volatile("cp.async.cg.shared.global [%0], [%1], 16;" :: "r"(dst), "l"(src));
}
#define CP_COMMIT()  asm volatile("cp.async.commit_group;" ::: "memory")
#define CP_WAIT(n)   asm volatile("cp.async.wait_group %0;" :: "n"(n) : "memory")

// ---------------- split fp32 -> bf16 hi + bf16 lo ----------------
// MODE 0: x. MODE 1..4: weights.
template<int MODE>
__global__ void conv_split(const float* __restrict__ src, int n) {
    const int i = blockIdx.x * 256 + threadIdx.x;
    if (i >= n) return;
    const float v = src[i];
    const __nv_bfloat16 h = __float2bfloat16(v);
    const __nv_bfloat16 l = __float2bfloat16(v - __bfloat162float(h));
    if (MODE == 0) { g_xh[i] = h; g_xl[i] = l; }
    else           { g_wh[MODE-1][i] = h; g_wl[MODE-1][i] = l; }
}

// ---------------- split-bf16 tensor-core GEMM, cp.async 2-stage pipeline ----------------
// C = A @ W^T. 128x128 CTA tile, 8 warps (2M x 4N), warp tile 64x32.
// MODE 0/1/2: A = x-split, C = g_q/g_k/g_v. MODE 3: A = attn-split (g_ath/g_atl), C = Cout.
#define KC      32
#define LDSROW  40                       // bf16 elems per smem row (80 B)
#define TILE_B  (128 * LDSROW * 2)       // 10240 B per tile
#define STAGE_B (4 * TILE_B)             // 40960 B per stage (Ah,Al,Bh,Bl)
#define NKC     (DIM / KC)               // 32

template<int MODE>
__global__ __launch_bounds__(256, 2)
void bgemm_mma(float* __restrict__ Cout) {
    extern __shared__ __nv_bfloat16 smb[];
    const uint32_t sb = smem_u32(smb);

    const __nv_bfloat16* __restrict__ Ah = (MODE == 3) ? g_ath : g_xh;
    const __nv_bfloat16* __restrict__ Al = (MODE == 3) ? g_atl : g_xl;
    const __nv_bfloat16* __restrict__ Bh = g_wh[MODE];
    const __nv_bfloat16* __restrict__ Bl = g_wl[MODE];
    float* C = (MODE == 0) ? g_q : (MODE == 1) ? g_k : (MODE == 2) ? g_v : Cout;

    const int bm = blockIdx.y * 128, bn = blockIdx.x * 128;
    const int tid = threadIdx.x, wid = tid >> 5, lane = tid & 31;
    const int wm = (wid & 1) * 64;
    const int wn = (wid >> 1) * 32;

    float acc[4][4][4];
#pragma unroll
    for (int i = 0; i < 4; i++)
#pragma unroll
        for (int j = 0; j < 4; j++)
#pragma unroll
            for (int r = 0; r < 4; r++) acc[i][j][r] = 0.f;

    const int a_row = lane & 15, a_koff = (lane >> 4) * 8;
    const int b_row = lane & 7,  b_koff = ((lane >> 3) & 1) * 8;

    // per-thread cp.async assignments: e in {tid, tid+256} -> row r = e>>2, col8 = (e&3)*8
    const int r0_ = tid >> 2,        c0_ = (tid & 3) * 8;
    const int r1_ = (tid + 256) >> 2, c1_ = c0_;        // (e&3) identical for e and e+256

    auto issue_stage = [&](int kc, int stage) {
        const uint32_t st = sb + stage * STAGE_B;
        const size_t ka = (size_t)kc * KC;
#pragma unroll
        for (int half = 0; half < 2; half++) {
            const int r = half ? r1_ : r0_;
            const int c8 = half ? c1_ : c0_;
            const uint32_t so = (uint32_t)(r * LDSROW + c8) * 2;
            const size_t ga = (size_t)(bm + r) * DIM + ka + c8;
            const size_t gb = (size_t)(bn + r) * DIM + ka + c8;
            cp_async16(st + 0*TILE_B + so, Ah + ga);
            cp_async16(st + 1*TILE_B + so, Al + ga);
            cp_async16(st + 2*TILE_B + so, Bh + gb);
            cp_async16(st + 3*TILE_B + so, Bl + gb);
        }
    };

    issue_stage(0, 0);
    CP_COMMIT();

    for (int kc = 0; kc < NKC; kc++) {
        if (kc + 1 < NKC) {
            issue_stage(kc + 1, (kc + 1) & 1);
            CP_COMMIT();
            CP_WAIT(1);
        } else {
            CP_WAIT(0);
        }
        __syncthreads();

        const uint32_t st = sb + (kc & 1) * STAGE_B;
        const uint32_t ah = st, al = st + TILE_B, bh_ = st + 2*TILE_B, bl_ = st + 3*TILE_B;

#pragma unroll
        for (int ks = 0; ks < KC / 16; ks++) {
            const int k0 = ks * 16;
            uint32_t afr[4][4], bfr[4][2];

            // term 1: Ah * Bh
#pragma unroll
            for (int im = 0; im < 4; im++)
                ldsm_x4(afr[im], ah + (uint32_t)((wm + im*16 + a_row) * LDSROW + k0 + a_koff) * 2);
#pragma unroll
            for (int in = 0; in < 4; in++)
                ldsm_x2(bfr[in], bh_ + (uint32_t)((wn + in*8 + b_row) * LDSROW + k0 + b_koff) * 2);
#pragma unroll
            for (int im = 0; im < 4; im++)
#pragma unroll
                for (int in = 0; in < 4; in++)
                    mma_bf16(acc[im][in], afr[im], bfr[in]);

            // term 2: Ah * Bl
#pragma unroll
            for (int in = 0; in < 4; in++)
                ldsm_x2(bfr[in], bl_ + (uint32_t)((wn + in*8 + b_row) * LDSROW + k0 + b_koff) * 2);
#pragma unroll
            for (int im = 0; im < 4; im++)
#pragma unroll
                for (int in = 0; in < 4; in++)
                    mma_bf16(acc[im][in], afr[im], bfr[in]);

            // term 3: Al * Bh
#pragma unroll
            for (int im = 0; im < 4; im++)
                ldsm_x4(afr[im], al + (uint32_t)((wm + im*16 + a_row) * LDSROW + k0 + a_koff) * 2);
#pragma unroll
            for (int in = 0; in < 4; in++)
                ldsm_x2(bfr[in], bh_ + (uint32_t)((wn + in*8 + b_row) * LDSROW + k0 + b_koff) * 2);
#pragma unroll
            for (int im = 0; im < 4; im++)
#pragma unroll
                for (int in = 0; in < 4; in++)
                    mma_bf16(acc[im][in], afr[im], bfr[in]);
        }
        __syncthreads();
    }

    const int er = lane >> 2, ec = (lane & 3) * 2;
#pragma unroll
    for (int im = 0; im < 4; im++)
#pragma unroll
        for (int in = 0; in < 4; in++) {
            const size_t r0 = (size_t)(bm + wm + im*16 + er) * DIM + (bn + wn + in*8 + ec);
            const size_t r1 = r0 + 8 * DIM;
            C[r0]     = acc[im][in][0];
            C[r0 + 1] = acc[im][in][1];
            C[r1]     = acc[im][in][2];
            C[r1 + 1] = acc[im][in][3];
        }
}

// ---------------- rope tables (verified) ----------------
__global__ void rope_tables() {
    const int idx = blockIdx.x * 256 + threadIdx.x;
    const int s = idx >> 5, i = idx & 31;
    const double inv = pow(10000.0, -((double)(2*i)) / 64.0);
    const double f = (double)s * inv;
    g_cos[s][i] = (float)cos(f);  g_cos[s][i+32] = (float)cos(f);
    g_sin[s][i] = (float)sin(f);  g_sin[s][i+32] = (float)sin(f);
}

// ---------------- rope apply (verified) ----------------
__global__ void rope_apply() {
    const int idx = blockIdx.x * 256 + threadIdx.x;
    const int i = idx & 31;
    const int h = (idx >> 5) & 15;
    const int m = idx >> 9;
    const int s = m & (SEQ-1);
    const float c  = g_cos[s][i];
    const float sn = g_sin[s][i];
    const size_t base = (size_t)m * DIM + h*HD + i;
    float x1 = g_q[base], x2 = g_q[base + 32];
    g_q[base]      = x1*c - x2*sn;
    g_q[base + 32] = x2*c + x1*sn;
    x1 = g_k[base]; x2 = g_k[base + 32];
    g_k[base]      = x1*c - x2*sn;
    g_k[base + 32] = x2*c + x1*sn;
}

// ---------------- fused flash attention (verified R6; epilogue now emits bf16 split) ----------------
__global__ __launch_bounds__(256)
void flash_kernel() {
    extern __shared__ float smf[];
    float (*Qs)[65]  = (float(*)[65])smf;
    float (*KVs)[65] = (float(*)[65])(smf + 64*65);
    float (*Ps)[65]  = (float(*)[65])(smf + 2*64*65);

    const int qt = blockIdx.x;
    const int bh = blockIdx.y;
    const int b = bh / NH, h = bh % NH;
    const int tid = threadIdx.x;
    const int ty = tid >> 4, tx = tid & 15;

    for (int e = tid; e < 64*64; e += 256) {
        int r = e >> 6, d = e & 63;
        Qs[r][d] = g_q[(size_t)(b*SEQ + qt*64 + r) * DIM + h*HD + d];
    }

    float mrow[4], lrow[4], O[4][4];
#pragma unroll
    for (int i = 0; i < 4; i++) {
        mrow[i] = -1e30f; lrow[i] = 0.f;
#pragma unroll
        for (int j = 0; j < 4; j++) O[i][j] = 0.f;
    }

    for (int kt = 0; kt <= qt; kt++) {
        __syncthreads();
        for (int e = tid; e < 64*64; e += 256) {
            int r = e >> 6, d = e & 63;
            KVs[r][d] = g_k[(size_t)(b*SEQ + kt*64 + r) * DIM + h*HD + d];
        }
        __syncthreads();

        float s[4][4];
#pragma unroll
        for (int i = 0; i < 4; i++)
#pragma unroll
            for (int j = 0; j < 4; j++) s[i][j] = 0.f;
        for (int d = 0; d < 64; d++) {
            float a[4], bb[4];
#pragma unroll
            for (int i = 0; i < 4; i++) a[i]  = Qs[ty*4 + i][d];
#pragma unroll
            for (int j = 0; j < 4; j++) bb[j] = KVs[tx*4 + j][d];
#pragma unroll
            for (int i = 0; i < 4; i++)
#pragma unroll
                for (int j = 0; j < 4; j++)
                    s[i][j] = fmaf(a[i], bb[j], s[i][j]);
        }
        const bool diag = (kt == qt);
#pragma unroll
        for (int i = 0; i < 4; i++)
#pragma unroll
            for (int j = 0; j < 4; j++) {
                s[i][j] *= 0.125f;
                if (diag && (tx*4 + j > ty*4 + i)) s[i][j] = -1e30f;
            }

#pragma unroll
        for (int i = 0; i < 4; i++) {
            float tm = fmaxf(fmaxf(s[i][0], s[i][1]), fmaxf(s[i][2], s[i][3]));
#pragma unroll
            for (int off = 8; off >= 1; off >>= 1)
                tm = fmaxf(tm, __shfl_xor_sync(0xffffffffu, tm, off, 16));
            const float mn = fmaxf(mrow[i], tm);
            const float alpha = __expf(mrow[i] - mn);
            float rs = 0.f;
#pragma unroll
            for (int j = 0; j < 4; j++) {
                s[i][j] = __expf(s[i][j] - mn);
                rs += s[i][j];
            }
#pragma unroll
            for (int off = 8; off >= 1; off >>= 1)
                rs += __shfl_xor_sync(0xffffffffu, rs, off, 16);
            lrow[i] = lrow[i] * alpha + rs;
            mrow[i] = mn;
#pragma unroll
            for (int j = 0; j < 4; j++) O[i][j] *= alpha;
        }

        __syncthreads();
        for (int e = tid; e < 64*64; e += 256) {
            int r = e >> 6, c = e & 63;
            KVs[r][c] = g_v[(size_t)(b*SEQ + kt*64 + r) * DIM + h*HD + c];
        }
#pragma unroll
        for (int i = 0; i < 4; i++)
#pragma unroll
            for (int j = 0; j < 4; j++)
                Ps[ty*4 + i][tx*4 + j] = s[i][j];
        __syncthreads();

        for (int kk = 0; kk < 64; kk++) {
            float p[4], vv[4];
#pragma unroll
            for (int i = 0; i < 4; i++) p[i]  = Ps[ty*4 + i][kk];
#pragma unroll
            for (int j = 0; j < 4; j++) vv[j] = KVs[kk][tx*4 + j];
#pragma unroll
            for (int i = 0; i < 4; i++)
#pragma unroll
                for (int j = 0; j < 4; j++)
                    O[i][j] = fmaf(p[i], vv[j], O[i][j]);
        }
    }

    // epilogue: hi/lo split written directly (replaces conv_split<5> + g_attn round-trip)
#pragma unroll
    for (int i = 0; i < 4; i++) {
        const float inv = 1.0f / lrow[i];
        const size_t base = (size_t)(b*SEQ + qt*64 + ty*4 + i) * DIM + h*HD + tx*4;
#pragma unroll
        for (int j = 0; j < 4; j++) {
            const float o = O[i][j] * inv;
            const __nv_bfloat16 hh = __float2bfloat16(o);
            g_ath[base + j] = hh;
            g_atl[base + j] = __float2bfloat16(o - __bfloat162float(hh));
        }
    }
}

// ---------------- launch ----------------
extern "C" void kernel_launch(void* const* d_in, const int* in_sizes, int n_in,
                              void* d_out, int out_size) {
    const float* x  = (const float*)d_in[0];
    const float* Wq = (const float*)d_in[1];
    const float* Wk = (const float*)d_in[2];
    const float* Wv = (const float*)d_in[3];
    const float* Wo = (const float*)d_in[4];
    float* out = (float*)d_out;

    const int NX = MROWS * DIM;
    const int NW = DIM * DIM;

    conv_split<0><<<(NX + 255)/256, 256>>>(x,  NX);
    conv_split<1><<<(NW + 255)/256, 256>>>(Wq, NW);
    conv_split<2><<<(NW + 255)/256, 256>>>(Wk, NW);
    conv_split<3><<<(NW + 255)/256, 256>>>(Wv, NW);
    conv_split<4><<<(NW + 255)/256, 256>>>(Wo, NW);

    const int gsmem = 2 * STAGE_B;   // 81,920 B
    cudaFuncSetAttribute(bgemm_mma<0>, cudaFuncAttributeMaxDynamicSharedMemorySize, gsmem);
    cudaFuncSetAttribute(bgemm_mma<1>, cudaFuncAttributeMaxDynamicSharedMemorySize, gsmem);
    cudaFuncSetAttribute(bgemm_mma<2>, cudaFuncAttributeMaxDynamicSharedMemorySize, gsmem);
    cudaFuncSetAttribute(bgemm_mma<3>, cudaFuncAttributeMaxDynamicSharedMemorySize, gsmem);

    const dim3 gg(DIM/128, MROWS/128);   // (8, 64)
    bgemm_mma<0><<<gg, 256, gsmem>>>(nullptr);
    bgemm_mma<1><<<gg, 256, gsmem>>>(nullptr);
    bgemm_mma<2><<<gg, 256, gsmem>>>(nullptr);

    rope_tables<<<(SEQ*32)/256, 256>>>();
    rope_apply<<<((size_t)MROWS*NH*32)/256, 256>>>();

    const int fsmem = 3 * 64 * 65 * sizeof(float);
    cudaFuncSetAttribute(flash_kernel, cudaFuncAttributeMaxDynamicSharedMemorySize, fsmem);
    flash_kernel<<<dim3(SEQ/64, BATCH*NH), 256, fsmem>>>();

    bgemm_mma<3><<<gg, 256, gsmem>>>(out);
}